// round 1
// baseline (speedup 1.0000x reference)
#include <cuda_runtime.h>

#define BB   256
#define TT   1024
#define SS   7
#define HH   64
#define LL   4
#define OO   3
#define BETA 0.8f
#define TH   1.0f

// One CTA per batch element. Threads 0..255: (layer l = tid>>6, unit h = tid&63),
// each owns membrane m[l][h] and the 64-float weight row feeding it, in registers.
// Threads 256..258: output-layer dot products. Layers are pipelined across
// timesteps: at stage s, layer l processes t = s - l, reading spikes produced by
// layer l-1 at stage s-1 from a double-buffered SMEM spike array. One
// __syncthreads per stage.
__global__ __launch_bounds__(288, 2)
void snn_pipeline_kernel(const float* __restrict__ x,
                         const float* __restrict__ hidden0,
                         const float* __restrict__ w1,
                         const float* __restrict__ b1,
                         const float* __restrict__ w_h,
                         const float* __restrict__ b_h,
                         const float* __restrict__ w_out,
                         const float* __restrict__ b_out,
                         float* __restrict__ out_outputs,   // [B,T,OO]
                         float* __restrict__ out_hidden,    // [B,T,LL,HH]
                         float* __restrict__ out_xcopy)     // [B,T,SS]
{
    const int b   = blockIdx.x;
    const int tid = threadIdx.x;

    __shared__ float spk[2][LL][HH];   // double-buffered spike vectors

    // ---- copy this batch's x slice to the output buffer (coalesced float4) ----
    {
        const float4* xs4 = (const float4*)(x + (size_t)b * TT * SS);
        float4*       xo4 = (float4*)(out_xcopy + (size_t)b * TT * SS);
        const int n4 = TT * SS / 4;  // 1792
        for (int i = tid; i < n4; i += blockDim.x) xo4[i] = xs4[i];
    }

    const int  l        = tid >> 6;
    const int  h        = tid & 63;
    const bool is_layer = (tid < LL * HH);
    const bool is_out   = (tid >= LL * HH) && (tid < LL * HH + OO);

    float wrow[HH];
    float bias = 0.0f;
    float m    = 0.0f;

    if (is_layer) {
        // initial membrane = hidden_states[b, 0, l, h]
        m = hidden0[(size_t)b * TT * LL * HH + (size_t)l * HH + h];
        if (l == 0) {
            #pragma unroll
            for (int k = 0; k < SS; k++) wrow[k] = w1[h * SS + k];
            bias = b1[h];
        } else {
            #pragma unroll
            for (int i = 0; i < HH; i++) wrow[i] = w_h[((size_t)(l - 1) * HH + h) * HH + i];
            bias = b_h[(l - 1) * HH + h];
        }
    } else if (is_out) {
        const int j = tid - LL * HH;
        #pragma unroll
        for (int i = 0; i < HH; i++) wrow[i] = w_out[j * HH + i];
        bias = b_out[j];
    }

    __syncthreads();

    const float*  xb       = x + (size_t)b * TT * SS;
    const size_t  hid_base = (size_t)b * TT * LL * HH;
    float*        outs     = out_outputs + (size_t)b * TT * OO;

    int cur = 0;  // buffer written this stage; readers use cur^1 (last stage's writes)

    for (int s = 0; s < TT + LL; s++) {
        if (is_layer) {
            const int t = s - l;
            if (t >= 0 && t < TT) {
                float c = bias;
                if (l == 0) {
                    const float* xr = xb + t * SS;
                    #pragma unroll
                    for (int k = 0; k < SS; k++) c = fmaf(xr[k], wrow[k], c);
                } else {
                    const float* sp = spk[cur ^ 1][l - 1];
                    float a0 = 0.f, a1 = 0.f, a2 = 0.f, a3 = 0.f;
                    #pragma unroll
                    for (int i = 0; i < HH; i += 4) {
                        float4 sv = *(const float4*)(sp + i);
                        a0 = fmaf(sv.x, wrow[i + 0], a0);
                        a1 = fmaf(sv.y, wrow[i + 1], a1);
                        a2 = fmaf(sv.z, wrow[i + 2], a2);
                        a3 = fmaf(sv.w, wrow[i + 3], a3);
                    }
                    c += (a0 + a1) + (a2 + a3);
                }
                const float reset = (m > TH) ? TH : 0.0f;
                const float m_new = fmaf(BETA, m, c) - reset;
                const float sv    = (m_new > TH) ? 1.0f : 0.0f;
                m = m_new;
                spk[cur][l][h] = sv;
                out_hidden[hid_base + (size_t)t * (LL * HH) + l * HH + h] = m_new;
            }
        } else if (is_out) {
            const int t = s - LL;  // uses layer-3 spikes written at stage s-1 (t = s-4)
            if (t >= 0) {
                const int    j  = tid - LL * HH;
                const float* sp = spk[cur ^ 1][LL - 1];
                float a0 = 0.f, a1 = 0.f, a2 = 0.f, a3 = 0.f;
                #pragma unroll
                for (int i = 0; i < HH; i += 4) {
                    float4 sv = *(const float4*)(sp + i);
                    a0 = fmaf(sv.x, wrow[i + 0], a0);
                    a1 = fmaf(sv.y, wrow[i + 1], a1);
                    a2 = fmaf(sv.z, wrow[i + 2], a2);
                    a3 = fmaf(sv.w, wrow[i + 3], a3);
                }
                outs[(size_t)t * OO + j] = bias + (a0 + a1) + (a2 + a3);
            }
        }
        __syncthreads();
        cur ^= 1;
    }
}

extern "C" void kernel_launch(void* const* d_in, const int* in_sizes, int n_in,
                              void* d_out, int out_size) {
    // metadata order: x, hidden_states, prev_obs, w1, b1, w_h, b_h, w_out, b_out
    const float* x       = (const float*)d_in[0];
    const float* hidden0 = (const float*)d_in[1];
    // d_in[2] = prev_obs (unused by reference)
    const float* w1      = (const float*)d_in[3];
    const float* b1      = (const float*)d_in[4];
    const float* w_h     = (const float*)d_in[5];
    const float* b_h     = (const float*)d_in[6];
    const float* w_out   = (const float*)d_in[7];
    const float* b_out   = (const float*)d_in[8];

    float* out_outputs = (float*)d_out;                                  // B*T*OO
    float* out_hidden  = out_outputs + (size_t)BB * TT * OO;             // B*T*LL*HH
    float* out_xcopy   = out_hidden + (size_t)BB * TT * LL * HH;         // B*T*SS

    snn_pipeline_kernel<<<BB, 288>>>(x, hidden0, w1, b1, w_h, b_h, w_out, b_out,
                                     out_outputs, out_hidden, out_xcopy);
}